// round 15
// baseline (speedup 1.0000x reference)
#include <cuda_runtime.h>

#define BB 4
#define NN 8192
#define CC 64
#define OUTD 64
#define KNNK 36
#define BN (BB*NN)
#define KBLK 128
#define SBLK 256               // threads per block for thresh/select
#define NSPLIT 4
#define QPART (NN/NSPLIT)      // 2048 candidates per split
#define SAMPLE 512             // threshold sample size
#define PKEEP 14               // threshold = 14th smallest of sample
#define CAP 128                // survivor capacity per thread per quarter
#define FINF 3.402823466e38f

// Device scratch (allocation-free rule: __device__ globals)
// Survivor scratch is TRANSPOSED: [h*CAP + slot][query] so that both the
// select dump and the reduce scan are (near-)coalesced across lanes.
__device__ float4 g_xyz4[BN];               // (sq, x, y, z) packed per point
__device__ float  g_vfeat[BN*OUTD];         // relu([feature,xyz] @ W_v + b_v)
__device__ float  g_T[BN];                  // per-query collect threshold
__device__ float  g_sd[(size_t)NSPLIT*CAP*BN]; // survivor distances [slot][q]
__device__ int    g_si[(size_t)NSPLIT*CAP*BN]; // survivor indices  [slot][q]
__device__ int    g_cnt[NSPLIT*BN];         // raw survivor count per (quarter,q)
__device__ int    g_knn[BN*KNNK];           // final top-36 indices
__device__ unsigned char g_fail[BN];        // per-query fallback flag

// ---------------------------------------------------------------------------
__global__ void pack_xyz_kernel(const float* __restrict__ xyz) {
    int i = blockIdx.x * blockDim.x + threadIdx.x;
    if (i >= BN) return;
    float x = xyz[3*i], y = xyz[3*i+1], z = xyz[3*i+2];
    g_xyz4[i] = make_float4(x*x + y*y + z*z, x, y, z);
}

// ---------------------------------------------------------------------------
// v_feat = relu(concat([feature, xyz]) @ W_v + b_v)   (B,N,64)
// ---------------------------------------------------------------------------
__global__ __launch_bounds__(256) void vfeat_kernel(
    const float* __restrict__ feature,
    const float* __restrict__ xyz,
    const float* __restrict__ Wv,
    const float* __restrict__ bv)
{
    __shared__ float fsh[4][68];
    int sub = threadIdx.x >> 6;
    int t   = threadIdx.x & 63;
    int p   = blockIdx.x * 4 + sub;
    fsh[sub][t] = feature[p*64 + t];
    if (t < 3) fsh[sub][64 + t] = xyz[p*3 + t];
    __syncthreads();
    const float* f = fsh[sub];
    float acc = bv[t];
    #pragma unroll
    for (int c = 0; c < 67; c++)
        acc = fmaf(f[c], Wv[c*64 + t], acc);
    g_vfeat[p*64 + t] = fmaxf(acc, 0.0f);
}

// ---------------------------------------------------------------------------
__device__ __forceinline__ void topk_insert_eq(
    float d, int idx, float* kd, int* ki, float& worst)
{
    #pragma unroll
    for (int s = 0; s < KNNK; s++) {
        bool h = (kd[s] == worst);
        kd[s] = h ? d   : kd[s];
        ki[s] = h ? idx : ki[s];
    }
    float w = kd[0];
    #pragma unroll
    for (int s = 1; s < KNNK; s++)
        w = fmaxf(w, kd[s]);
    worst = w;
}

__device__ __forceinline__ float dist3(const float4& c, float nx, float ny, float nz) {
    float d = fmaf(nx, c.y, c.x);
    d = fmaf(ny, c.z, d);
    return fmaf(nz, c.w, d);
}

// ---------------------------------------------------------------------------
// Threshold kernel: per query, T = 14th smallest distance among the batch's
// first 512 candidates. Sample is smem-resident (8KB, one barrier).
// ---------------------------------------------------------------------------
__global__ __launch_bounds__(SBLK) void knn_thresh_kernel() {
    __shared__ float4 smp[SAMPLE];
    const unsigned FULL = 0xffffffffu;

    int tid = threadIdx.x;
    int q = blockIdx.x * SBLK + tid;
    int b = q >> 13;

    const float4* __restrict__ cand = g_xyz4 + b * NN;
    for (int i = tid; i < SAMPLE; i += SBLK) smp[i] = cand[i];
    __syncthreads();

    float4 me = g_xyz4[q];
    float nx = -2.0f * me.y, ny = -2.0f * me.z, nz = -2.0f * me.w;

    float pd[PKEEP];
    #pragma unroll
    for (int s = 0; s < PKEEP; s++)
        pd[s] = dist3(smp[s], nx, ny, nz);
    float worstA = pd[0];
    #pragma unroll
    for (int s = 1; s < PKEEP; s++) worstA = fmaxf(worstA, pd[s]);

    for (int js = 0; js < SAMPLE; js += 32) {
        unsigned m0 = 0, m1 = 0;
        #pragma unroll
        for (int jj = 0; jj < 16; jj++) {
            float d = dist3(smp[js + jj], nx, ny, nz);
            m0 |= (d < worstA) ? (1u << jj) : 0u;
        }
        #pragma unroll
        for (int jj = 16; jj < 32; jj++) {
            float d = dist3(smp[js + jj], nx, ny, nz);
            m1 |= (d < worstA) ? (1u << jj) : 0u;
        }
        unsigned mask = m0 | m1;
        if (js == 0) mask &= 0xFFFFC000u;  // first 14 already filled

        if (__any_sync(FULL, mask != 0u)) {
            while (mask) {
                int jj = __ffs(mask) - 1;
                mask &= mask - 1;
                float d = dist3(smp[js + jj], nx, ny, nz);
                if (d < worstA) {
                    #pragma unroll
                    for (int s = 0; s < PKEEP; s++) {
                        bool hh = (pd[s] == worstA);
                        pd[s] = hh ? d : pd[s];
                    }
                    float w = pd[0];
                    #pragma unroll
                    for (int s = 1; s < PKEEP; s++) w = fmaxf(w, pd[s]);
                    worstA = w;
                }
            }
        }
    }
    g_T[q] = worstA;
}

// ---------------------------------------------------------------------------
// Select = scan + dump. Quarter tile smem-resident; per-candidate bitmask
// scan; survivors (d, idx) dumped to TRANSPOSED global scratch (coalesced).
// ---------------------------------------------------------------------------
__global__ __launch_bounds__(SBLK) void knn_select_kernel() {
    __shared__ float4 qt[QPART];           // 32KB quarter tile
    const unsigned FULL = 0xffffffffu;

    int tid = threadIdx.x;
    int q = blockIdx.x * SBLK + tid;
    int h = blockIdx.y;
    int b = q >> 13;

    const float4* __restrict__ cand = g_xyz4 + b * NN + h * QPART;
    for (int i = tid; i < QPART; i += SBLK) qt[i] = cand[i];
    __syncthreads();

    float4 me = g_xyz4[q];
    float nx = -2.0f * me.y, ny = -2.0f * me.z, nz = -2.0f * me.w;
    const float T = g_T[q];
    const int idx_off = h * QPART;

    const size_t row0 = (size_t)h * CAP * BN + q;   // + slot*BN
    int cnt = 0;

    for (int js = 0; js < QPART; js += 32) {
        unsigned m0 = 0, m1 = 0, m2 = 0, m3 = 0;
        #pragma unroll
        for (int jj = 0; jj < 8; jj++) {
            float d = dist3(qt[js + jj], nx, ny, nz);
            m0 |= (d <= T) ? (1u << jj) : 0u;
        }
        #pragma unroll
        for (int jj = 8; jj < 16; jj++) {
            float d = dist3(qt[js + jj], nx, ny, nz);
            m1 |= (d <= T) ? (1u << jj) : 0u;
        }
        #pragma unroll
        for (int jj = 16; jj < 24; jj++) {
            float d = dist3(qt[js + jj], nx, ny, nz);
            m2 |= (d <= T) ? (1u << jj) : 0u;
        }
        #pragma unroll
        for (int jj = 24; jj < 32; jj++) {
            float d = dist3(qt[js + jj], nx, ny, nz);
            m3 |= (d <= T) ? (1u << jj) : 0u;
        }
        unsigned mask = (m0 | m1) | (m2 | m3);
        if (__any_sync(FULL, mask != 0u)) {
            while (mask) {
                int jj = __ffs(mask) - 1;
                mask &= mask - 1;
                if (cnt < CAP) {
                    float d = dist3(qt[js + jj], nx, ny, nz);
                    size_t a = row0 + (size_t)cnt * BN;
                    g_sd[a] = d;
                    g_si[a] = idx_off + js + jj;
                }
                cnt++;
            }
        }
    }
    g_cnt[(size_t)h * BN + q] = cnt;
}

// ---------------------------------------------------------------------------
// Reduce: per query, exact top-36 over all quarters' survivors -> g_knn.
// Transposed scratch => coalesced loads across lanes. Eq-replace insert
// seeded with DISTINCT descending sentinels.
// ---------------------------------------------------------------------------
__global__ __launch_bounds__(KBLK) void knn_reduce_kernel() {
    int q = blockIdx.x * KBLK + threadIdx.x;

    int c[NSPLIT];
    int total = 0;
    bool over = false;
    #pragma unroll
    for (int h = 0; h < NSPLIT; h++) {
        c[h] = g_cnt[(size_t)h * BN + q];
        total += c[h];
        over |= (c[h] > CAP);
    }
    if (total < KNNK || over) {
        g_fail[q] = 1;
        return;
    }
    g_fail[q] = 0;

    float kd[KNNK];
    int   ki[KNNK];
    #pragma unroll
    for (int s = 0; s < KNNK; s++) {
        kd[s] = 1.0e30f * (float)(KNNK - s);   // distinct descending sentinels
        ki[s] = 0;
    }
    float worst = kd[0];

    #pragma unroll
    for (int h = 0; h < NSPLIT; h++) {
        const size_t row0 = (size_t)h * CAP * BN + q;
        int ch = c[h];
        for (int it = 0; it < ch; it++) {
            size_t a = row0 + (size_t)it * BN;
            float d = g_sd[a];
            if (d < worst) {
                int idx = g_si[a];
                topk_insert_eq(d, idx, kd, ki, worst);
            }
        }
    }

    #pragma unroll
    for (int s = 0; s < KNNK; s++)
        g_knn[(size_t)q * KNNK + s] = ki[s];
}

// ---------------------------------------------------------------------------
// Order-preserving float -> uint map for bit-bisection selection.
// ---------------------------------------------------------------------------
__device__ __forceinline__ unsigned f2mono(float f) {
    unsigned u = __float_as_uint(f);
    return (u & 0x80000000u) ? ~u : (u | 0x80000000u);
}

// ---------------------------------------------------------------------------
// Fallback: flagged queries (expected ~30/run) get an exact whole-N warp
// bisection; result written straight to g_knn.
// ---------------------------------------------------------------------------
__global__ __launch_bounds__(KBLK) void knn_fallback_kernel() {
    __shared__ unsigned um[NN];            // 32KB distance cache
    __shared__ int fq[KBLK];
    __shared__ int fn;
    const unsigned FULL = 0xffffffffu;

    int tid = threadIdx.x;
    int q = blockIdx.x * KBLK + tid;

    if (tid == 0) fn = 0;
    __syncthreads();

    if (g_fail[q]) {
        int slot = atomicAdd(&fn, 1);
        fq[slot] = q;
    }
    __syncthreads();

    int nf = fn;
    for (int t = 0; t < nf; t++) {
        int fqq = fq[t];
        int b = fqq >> 13;
        float4 me = g_xyz4[fqq];
        float nx = -2.0f * me.y, ny = -2.0f * me.z, nz = -2.0f * me.w;
        const float4* __restrict__ cand = g_xyz4 + b * NN;

        for (int i = tid; i < NN; i += KBLK)
            um[i] = f2mono(dist3(cand[i], nx, ny, nz));
        __syncthreads();

        if (tid < 32) {
            int lane = tid;
            unsigned prefix = 0;
            for (int bit = 31; bit >= 0; bit--) {
                unsigned trial = prefix | ((1u << bit) - 1u);
                int cnt = 0;
                for (int i = 0; i < NN/32; i++)
                    cnt += (um[lane + 32*i] <= trial) ? 1 : 0;
                #pragma unroll
                for (int s = 16; s; s >>= 1)
                    cnt += __shfl_xor_sync(FULL, cnt, s);
                if (cnt < KNNK) prefix |= (1u << bit);
            }
            const unsigned V = prefix;

            size_t o = (size_t)fqq * KNNK;
            unsigned lt = (1u << lane) - 1u;
            int base = 0;
            for (int i = 0; i < NN/32 && base < KNNK; i++) {
                int j = lane + 32*i;
                bool hit = (um[j] <= V);
                unsigned m = __ballot_sync(FULL, hit);
                if (hit) {
                    int r = base + __popc(m & lt);
                    if (r < KNNK) g_knn[o + r] = j;
                }
                base += __popc(m);
            }
        }
        __syncthreads();
    }
}

// ---------------------------------------------------------------------------
// Attention + suffix GEMM (coalesced row reads + shuffle reduce), reads g_knn.
// ---------------------------------------------------------------------------
__global__ __launch_bounds__(256) void attn_kernel(
    const float* __restrict__ feature,
    const float* __restrict__ Wsuf,
    const float* __restrict__ bsuf,
    float* __restrict__ out)
{
    __shared__ float osh[8][64];
    const unsigned FULL = 0xffffffffu;
    int w    = threadIdx.x >> 5;
    int lane = threadIdx.x & 31;
    int p    = blockIdx.x * 8 + w;
    int b    = p >> 13;

    const float* frow = feature + (size_t)p * 64;
    float2 q2 = *(const float2*)(frow + 2*lane);

    int idxA = g_knn[(size_t)p*KNNK + lane];
    int idxB = (lane < 4) ? g_knn[(size_t)p*KNNK + 32 + lane] : 0;

    const float* fbase = feature + (size_t)b * NN * 64;
    float wA = 0.0f, wB = -3.4e38f;

    #pragma unroll
    for (int k = 0; k < KNNK; k++) {
        int j = (k < 32) ? __shfl_sync(FULL, idxA, k)
                         : __shfl_sync(FULL, idxB, k - 32);
        float2 f2 = *(const float2*)(fbase + (size_t)j * 64 + 2*lane);
        float part = fmaf(f2.x, q2.x, f2.y * q2.y);
        #pragma unroll
        for (int s = 16; s; s >>= 1)
            part += __shfl_xor_sync(FULL, part, s);
        if (k < 32) { if (lane == k)      wA = part; }
        else        { if (lane == k - 32) wB = part; }
    }

    float m = fmaxf(wA, (lane < 4) ? wB : -3.4e38f);
    #pragma unroll
    for (int s = 16; s; s >>= 1)
        m = fmaxf(m, __shfl_xor_sync(FULL, m, s));
    float eA = __expf(wA - m);
    float eB = (lane < 4) ? __expf(wB - m) : 0.0f;
    float ssum = eA + eB;
    #pragma unroll
    for (int s = 16; s; s >>= 1)
        ssum += __shfl_xor_sync(FULL, ssum, s);
    float inv = 1.0f / ssum;
    eA *= inv; eB *= inv;

    const float* vbase = g_vfeat + (size_t)b * NN * 64;
    float ox = 0.0f, oy = 0.0f;
    #pragma unroll
    for (int k = 0; k < KNNK; k++) {
        int j; float wk;
        if (k < 32) { j = __shfl_sync(FULL, idxA, k);      wk = __shfl_sync(FULL, eA, k); }
        else        { j = __shfl_sync(FULL, idxB, k - 32); wk = __shfl_sync(FULL, eB, k - 32); }
        float2 v2 = *(const float2*)(vbase + (size_t)j * 64 + 2*lane);
        ox = fmaf(wk, v2.x, ox);
        oy = fmaf(wk, v2.y, oy);
    }

    osh[w][2*lane]     = ox;
    osh[w][2*lane + 1] = oy;
    __syncwarp();
    float2 acc = *(const float2*)(bsuf + 2*lane);
    #pragma unroll 8
    for (int c = 0; c < 64; c++) {
        float oc = osh[w][c];
        float2 wv = *(const float2*)(Wsuf + c*64 + 2*lane);
        acc.x = fmaf(oc, wv.x, acc.x);
        acc.y = fmaf(oc, wv.y, acc.y);
    }
    *(float2*)(out + (size_t)p * 64 + 2*lane) = acc;
}

__global__ void tail_kernel(float* __restrict__ out, int out_size) {
    int i = BN*OUTD + blockIdx.x * blockDim.x + threadIdx.x;
    if (i < out_size) out[i] = (float)NN;
}

extern "C" void kernel_launch(void* const* d_in, const int* in_sizes, int n_in,
                              void* d_out, int out_size) {
    const float* feature = (const float*)d_in[0];
    const float* xyz     = (const float*)d_in[1];
    const float* Wv      = (const float*)d_in[2];
    const float* bv      = (const float*)d_in[3];
    const float* Wsuf    = (const float*)d_in[4];
    const float* bsuf    = (const float*)d_in[5];
    float* out = (float*)d_out;

    cudaFuncSetAttribute(knn_select_kernel,
                         cudaFuncAttributePreferredSharedMemoryCarveout, 100);
    cudaFuncSetAttribute(knn_thresh_kernel,
                         cudaFuncAttributePreferredSharedMemoryCarveout, 100);
    cudaFuncSetAttribute(knn_fallback_kernel,
                         cudaFuncAttributePreferredSharedMemoryCarveout, 100);

    pack_xyz_kernel<<<(BN + 255) / 256, 256>>>(xyz);
    vfeat_kernel<<<BN / 4, 256>>>(feature, xyz, Wv, bv);
    knn_thresh_kernel<<<BN / SBLK, SBLK>>>();
    dim3 kgrid(BN / SBLK, NSPLIT);
    knn_select_kernel<<<kgrid, SBLK>>>();
    knn_reduce_kernel<<<BN / KBLK, KBLK>>>();
    knn_fallback_kernel<<<BN / KBLK, KBLK>>>();
    attn_kernel<<<BN / 8, 256>>>(feature, Wsuf, bsuf, out);

    if (out_size > BN*OUTD) {
        int extra = out_size - BN*OUTD;
        tail_kernel<<<(extra + 255) / 256, 256>>>(out, out_size);
    }
}

// round 16
// speedup vs baseline: 1.5367x; 1.5367x over previous
#include <cuda_runtime.h>

#define BB 4
#define NN 8192
#define CC 64
#define OUTD 64
#define KNNK 36
#define BN (BB*NN)
#define KBLK 128
#define SBLK 256               // threads per block for thresh/select
#define NSPLIT 4
#define QPART (NN/NSPLIT)      // 2048 candidates per split
#define SAMPLE 512             // threshold sample size
#define PKEEP 14               // threshold = 14th smallest of sample
#define CAP 128                // survivor capacity per thread per quarter
#define RW 8                   // warps (queries) per reduce block
#define FINF 3.402823466e38f

// Device scratch (allocation-free rule: __device__ globals)
// Survivor scratch layout: [(h*BN + q)*CAP + slot] — per-query contiguous,
// which is COALESCED for the warp-per-query reduce (lane-varying slot).
__device__ float4 g_xyz4[BN];               // (sq, x, y, z) packed per point
__device__ float  g_vfeat[BN*OUTD];         // relu([feature,xyz] @ W_v + b_v)
__device__ float  g_T[BN];                  // per-query collect threshold
__device__ float  g_sd[(size_t)NSPLIT*BN*CAP]; // survivor distances
__device__ int    g_si[(size_t)NSPLIT*BN*CAP]; // survivor indices (batch-rel)
__device__ int    g_cnt[NSPLIT*BN];         // raw survivor count per (quarter,q)
__device__ int    g_knn[BN*KNNK];           // final top-36 indices
__device__ unsigned char g_fail[BN];        // per-query fallback flag

// ---------------------------------------------------------------------------
__global__ void pack_xyz_kernel(const float* __restrict__ xyz) {
    int i = blockIdx.x * blockDim.x + threadIdx.x;
    if (i >= BN) return;
    float x = xyz[3*i], y = xyz[3*i+1], z = xyz[3*i+2];
    g_xyz4[i] = make_float4(x*x + y*y + z*z, x, y, z);
}

// ---------------------------------------------------------------------------
// v_feat = relu(concat([feature, xyz]) @ W_v + b_v)   (B,N,64)
// ---------------------------------------------------------------------------
__global__ __launch_bounds__(256) void vfeat_kernel(
    const float* __restrict__ feature,
    const float* __restrict__ xyz,
    const float* __restrict__ Wv,
    const float* __restrict__ bv)
{
    __shared__ float fsh[4][68];
    int sub = threadIdx.x >> 6;
    int t   = threadIdx.x & 63;
    int p   = blockIdx.x * 4 + sub;
    fsh[sub][t] = feature[p*64 + t];
    if (t < 3) fsh[sub][64 + t] = xyz[p*3 + t];
    __syncthreads();
    const float* f = fsh[sub];
    float acc = bv[t];
    #pragma unroll
    for (int c = 0; c < 67; c++)
        acc = fmaf(f[c], Wv[c*64 + t], acc);
    g_vfeat[p*64 + t] = fmaxf(acc, 0.0f);
}

// ---------------------------------------------------------------------------
__device__ __forceinline__ float dist3(const float4& c, float nx, float ny, float nz) {
    float d = fmaf(nx, c.y, c.x);
    d = fmaf(ny, c.z, d);
    return fmaf(nz, c.w, d);
}

// Order-preserving float -> uint map for bit-bisection selection.
__device__ __forceinline__ unsigned f2mono(float f) {
    unsigned u = __float_as_uint(f);
    return (u & 0x80000000u) ? ~u : (u | 0x80000000u);
}

// ---------------------------------------------------------------------------
// Threshold kernel: per query, T = 14th smallest distance among the batch's
// first 512 candidates. Sample is smem-resident (8KB, one barrier).
// ---------------------------------------------------------------------------
__global__ __launch_bounds__(SBLK) void knn_thresh_kernel() {
    __shared__ float4 smp[SAMPLE];
    const unsigned FULL = 0xffffffffu;

    int tid = threadIdx.x;
    int q = blockIdx.x * SBLK + tid;
    int b = q >> 13;

    const float4* __restrict__ cand = g_xyz4 + b * NN;
    for (int i = tid; i < SAMPLE; i += SBLK) smp[i] = cand[i];
    __syncthreads();

    float4 me = g_xyz4[q];
    float nx = -2.0f * me.y, ny = -2.0f * me.z, nz = -2.0f * me.w;

    float pd[PKEEP];
    #pragma unroll
    for (int s = 0; s < PKEEP; s++)
        pd[s] = dist3(smp[s], nx, ny, nz);
    float worstA = pd[0];
    #pragma unroll
    for (int s = 1; s < PKEEP; s++) worstA = fmaxf(worstA, pd[s]);

    for (int js = 0; js < SAMPLE; js += 32) {
        unsigned m0 = 0, m1 = 0;
        #pragma unroll
        for (int jj = 0; jj < 16; jj++) {
            float d = dist3(smp[js + jj], nx, ny, nz);
            m0 |= (d < worstA) ? (1u << jj) : 0u;
        }
        #pragma unroll
        for (int jj = 16; jj < 32; jj++) {
            float d = dist3(smp[js + jj], nx, ny, nz);
            m1 |= (d < worstA) ? (1u << jj) : 0u;
        }
        unsigned mask = m0 | m1;
        if (js == 0) mask &= 0xFFFFC000u;  // first 14 already filled

        if (__any_sync(FULL, mask != 0u)) {
            while (mask) {
                int jj = __ffs(mask) - 1;
                mask &= mask - 1;
                float d = dist3(smp[js + jj], nx, ny, nz);
                if (d < worstA) {
                    #pragma unroll
                    for (int s = 0; s < PKEEP; s++) {
                        bool hh = (pd[s] == worstA);
                        pd[s] = hh ? d : pd[s];
                    }
                    float w = pd[0];
                    #pragma unroll
                    for (int s = 1; s < PKEEP; s++) w = fmaxf(w, pd[s]);
                    worstA = w;
                }
            }
        }
    }
    g_T[q] = worstA;
}

// ---------------------------------------------------------------------------
// Select = scan + dump. Quarter tile smem-resident; per-candidate bitmask
// scan; survivors (d, idx) dumped to per-query-contiguous global scratch.
// No top-36 arrays -> low register count -> high occupancy.
// ---------------------------------------------------------------------------
__global__ __launch_bounds__(SBLK) void knn_select_kernel() {
    __shared__ float4 qt[QPART];           // 32KB quarter tile
    const unsigned FULL = 0xffffffffu;

    int tid = threadIdx.x;
    int q = blockIdx.x * SBLK + tid;
    int h = blockIdx.y;
    int b = q >> 13;

    const float4* __restrict__ cand = g_xyz4 + b * NN + h * QPART;
    for (int i = tid; i < QPART; i += SBLK) qt[i] = cand[i];
    __syncthreads();

    float4 me = g_xyz4[q];
    float nx = -2.0f * me.y, ny = -2.0f * me.z, nz = -2.0f * me.w;
    const float T = g_T[q];
    const int idx_off = h * QPART;

    size_t obase = ((size_t)h * BN + q) * CAP;
    int cnt = 0;

    for (int js = 0; js < QPART; js += 32) {
        unsigned m0 = 0, m1 = 0, m2 = 0, m3 = 0;
        #pragma unroll
        for (int jj = 0; jj < 8; jj++) {
            float d = dist3(qt[js + jj], nx, ny, nz);
            m0 |= (d <= T) ? (1u << jj) : 0u;
        }
        #pragma unroll
        for (int jj = 8; jj < 16; jj++) {
            float d = dist3(qt[js + jj], nx, ny, nz);
            m1 |= (d <= T) ? (1u << jj) : 0u;
        }
        #pragma unroll
        for (int jj = 16; jj < 24; jj++) {
            float d = dist3(qt[js + jj], nx, ny, nz);
            m2 |= (d <= T) ? (1u << jj) : 0u;
        }
        #pragma unroll
        for (int jj = 24; jj < 32; jj++) {
            float d = dist3(qt[js + jj], nx, ny, nz);
            m3 |= (d <= T) ? (1u << jj) : 0u;
        }
        unsigned mask = (m0 | m1) | (m2 | m3);
        if (__any_sync(FULL, mask != 0u)) {
            while (mask) {
                int jj = __ffs(mask) - 1;
                mask &= mask - 1;
                if (cnt < CAP) {
                    float d = dist3(qt[js + jj], nx, ny, nz);
                    g_sd[obase + cnt] = d;
                    g_si[obase + cnt] = idx_off + js + jj;
                }
                cnt++;
            }
        }
    }
    g_cnt[(size_t)h * BN + q] = cnt;
}

// ---------------------------------------------------------------------------
// Reduce: WARP-PER-QUERY exact top-36 via ballot bit-bisection.
// Lane l holds survivors at global slots l+32*i (i<16) over the 4*CAP=512
// concatenated slots; invalid slots (>= that quarter's count) load as
// 0xFFFFFFFF. Bisection finds the exact 36th-smallest mono-uint; ballot-
// prefix compaction writes the 36 indices to g_knn. No insert bodies, no
// local memory, fully coalesced loads.
// ---------------------------------------------------------------------------
__global__ __launch_bounds__(RW*32) void knn_reduce_kernel() {
    const unsigned FULL = 0xffffffffu;
    int lane = threadIdx.x & 31;
    int w    = threadIdx.x >> 5;
    int q    = blockIdx.x * RW + w;

    int c[NSPLIT];
    int total = 0;
    bool over = false;
    #pragma unroll
    for (int h = 0; h < NSPLIT; h++) {
        c[h] = g_cnt[(size_t)h * BN + q];
        total += c[h];
        over |= (c[h] > CAP);
    }
    bool fail = (total < KNNK) || over;
    if (lane == 0) g_fail[q] = fail ? 1 : 0;
    if (fail) return;

    // load survivors as mono-uints (16 per lane, coalesced within each i)
    unsigned um[16];
    #pragma unroll
    for (int i = 0; i < 16; i++) {
        int g = lane + 32*i;            // 0..511
        int h = g >> 7;                 // CAP = 128
        int slot = g & (CAP - 1);
        bool valid = slot < c[h];
        um[i] = valid ? f2mono(g_sd[((size_t)h * BN + q) * CAP + slot])
                      : 0xFFFFFFFFu;
    }

    // bisection: V = 36th smallest
    unsigned prefix = 0;
    #pragma unroll
    for (int bit = 31; bit >= 0; bit--) {
        unsigned trial = prefix | ((1u << bit) - 1u);
        int cnt = 0;
        #pragma unroll
        for (int i = 0; i < 16; i++)
            cnt += (um[i] <= trial) ? 1 : 0;
        #pragma unroll
        for (int s = 16; s; s >>= 1)
            cnt += __shfl_xor_sync(FULL, cnt, s);
        if (cnt < KNNK) prefix |= (1u << bit);
    }
    const unsigned V = prefix;

    // compaction of the <=V set into g_knn slots 0..35
    unsigned lt = (1u << lane) - 1u;
    size_t o = (size_t)q * KNNK;
    int base = 0;
    for (int i = 0; i < 16; i++) {
        bool hit = (um[i] <= V);
        unsigned m = __ballot_sync(FULL, hit);
        if (hit) {
            int r = base + __popc(m & lt);
            if (r < KNNK) {
                int g = lane + 32*i;
                int h = g >> 7;
                int slot = g & (CAP - 1);
                g_knn[o + r] = g_si[((size_t)h * BN + q) * CAP + slot];
            }
        }
        base += __popc(m);
        if (base >= KNNK) break;     // uniform across warp
    }
}

// ---------------------------------------------------------------------------
// Fallback: flagged queries (expected ~30/run) get an exact whole-N warp
// bisection; result written straight to g_knn.
// ---------------------------------------------------------------------------
__global__ __launch_bounds__(KBLK) void knn_fallback_kernel() {
    __shared__ unsigned um[NN];            // 32KB distance cache
    __shared__ int fq[KBLK];
    __shared__ int fn;
    const unsigned FULL = 0xffffffffu;

    int tid = threadIdx.x;
    int q = blockIdx.x * KBLK + tid;

    if (tid == 0) fn = 0;
    __syncthreads();

    if (g_fail[q]) {
        int slot = atomicAdd(&fn, 1);
        fq[slot] = q;
    }
    __syncthreads();

    int nf = fn;
    for (int t = 0; t < nf; t++) {
        int fqq = fq[t];
        int b = fqq >> 13;
        float4 me = g_xyz4[fqq];
        float nx = -2.0f * me.y, ny = -2.0f * me.z, nz = -2.0f * me.w;
        const float4* __restrict__ cand = g_xyz4 + b * NN;

        for (int i = tid; i < NN; i += KBLK)
            um[i] = f2mono(dist3(cand[i], nx, ny, nz));
        __syncthreads();

        if (tid < 32) {
            int lane = tid;
            unsigned prefix = 0;
            for (int bit = 31; bit >= 0; bit--) {
                unsigned trial = prefix | ((1u << bit) - 1u);
                int cnt = 0;
                for (int i = 0; i < NN/32; i++)
                    cnt += (um[lane + 32*i] <= trial) ? 1 : 0;
                #pragma unroll
                for (int s = 16; s; s >>= 1)
                    cnt += __shfl_xor_sync(FULL, cnt, s);
                if (cnt < KNNK) prefix |= (1u << bit);
            }
            const unsigned V = prefix;

            size_t o = (size_t)fqq * KNNK;
            unsigned lt = (1u << lane) - 1u;
            int base = 0;
            for (int i = 0; i < NN/32 && base < KNNK; i++) {
                int j = lane + 32*i;
                bool hit = (um[j] <= V);
                unsigned m = __ballot_sync(FULL, hit);
                if (hit) {
                    int r = base + __popc(m & lt);
                    if (r < KNNK) g_knn[o + r] = j;
                }
                base += __popc(m);
            }
        }
        __syncthreads();
    }
}

// ---------------------------------------------------------------------------
// Attention + suffix GEMM (coalesced row reads + shuffle reduce), reads g_knn.
// ---------------------------------------------------------------------------
__global__ __launch_bounds__(256) void attn_kernel(
    const float* __restrict__ feature,
    const float* __restrict__ Wsuf,
    const float* __restrict__ bsuf,
    float* __restrict__ out)
{
    __shared__ float osh[8][64];
    const unsigned FULL = 0xffffffffu;
    int w    = threadIdx.x >> 5;
    int lane = threadIdx.x & 31;
    int p    = blockIdx.x * 8 + w;
    int b    = p >> 13;

    const float* frow = feature + (size_t)p * 64;
    float2 q2 = *(const float2*)(frow + 2*lane);

    int idxA = g_knn[(size_t)p*KNNK + lane];
    int idxB = (lane < 4) ? g_knn[(size_t)p*KNNK + 32 + lane] : 0;

    const float* fbase = feature + (size_t)b * NN * 64;
    float wA = 0.0f, wB = -3.4e38f;

    #pragma unroll
    for (int k = 0; k < KNNK; k++) {
        int j = (k < 32) ? __shfl_sync(FULL, idxA, k)
                         : __shfl_sync(FULL, idxB, k - 32);
        float2 f2 = *(const float2*)(fbase + (size_t)j * 64 + 2*lane);
        float part = fmaf(f2.x, q2.x, f2.y * q2.y);
        #pragma unroll
        for (int s = 16; s; s >>= 1)
            part += __shfl_xor_sync(FULL, part, s);
        if (k < 32) { if (lane == k)      wA = part; }
        else        { if (lane == k - 32) wB = part; }
    }

    float m = fmaxf(wA, (lane < 4) ? wB : -3.4e38f);
    #pragma unroll
    for (int s = 16; s; s >>= 1)
        m = fmaxf(m, __shfl_xor_sync(FULL, m, s));
    float eA = __expf(wA - m);
    float eB = (lane < 4) ? __expf(wB - m) : 0.0f;
    float ssum = eA + eB;
    #pragma unroll
    for (int s = 16; s; s >>= 1)
        ssum += __shfl_xor_sync(FULL, ssum, s);
    float inv = 1.0f / ssum;
    eA *= inv; eB *= inv;

    const float* vbase = g_vfeat + (size_t)b * NN * 64;
    float ox = 0.0f, oy = 0.0f;
    #pragma unroll
    for (int k = 0; k < KNNK; k++) {
        int j; float wk;
        if (k < 32) { j = __shfl_sync(FULL, idxA, k);      wk = __shfl_sync(FULL, eA, k); }
        else        { j = __shfl_sync(FULL, idxB, k - 32); wk = __shfl_sync(FULL, eB, k - 32); }
        float2 v2 = *(const float2*)(vbase + (size_t)j * 64 + 2*lane);
        ox = fmaf(wk, v2.x, ox);
        oy = fmaf(wk, v2.y, oy);
    }

    osh[w][2*lane]     = ox;
    osh[w][2*lane + 1] = oy;
    __syncwarp();
    float2 acc = *(const float2*)(bsuf + 2*lane);
    #pragma unroll 8
    for (int c = 0; c < 64; c++) {
        float oc = osh[w][c];
        float2 wv = *(const float2*)(Wsuf + c*64 + 2*lane);
        acc.x = fmaf(oc, wv.x, acc.x);
        acc.y = fmaf(oc, wv.y, acc.y);
    }
    *(float2*)(out + (size_t)p * 64 + 2*lane) = acc;
}

__global__ void tail_kernel(float* __restrict__ out, int out_size) {
    int i = BN*OUTD + blockIdx.x * blockDim.x + threadIdx.x;
    if (i < out_size) out[i] = (float)NN;
}

extern "C" void kernel_launch(void* const* d_in, const int* in_sizes, int n_in,
                              void* d_out, int out_size) {
    const float* feature = (const float*)d_in[0];
    const float* xyz     = (const float*)d_in[1];
    const float* Wv      = (const float*)d_in[2];
    const float* bv      = (const float*)d_in[3];
    const float* Wsuf    = (const float*)d_in[4];
    const float* bsuf    = (const float*)d_in[5];
    float* out = (float*)d_out;

    cudaFuncSetAttribute(knn_select_kernel,
                         cudaFuncAttributePreferredSharedMemoryCarveout, 100);
    cudaFuncSetAttribute(knn_thresh_kernel,
                         cudaFuncAttributePreferredSharedMemoryCarveout, 100);
    cudaFuncSetAttribute(knn_fallback_kernel,
                         cudaFuncAttributePreferredSharedMemoryCarveout, 100);

    pack_xyz_kernel<<<(BN + 255) / 256, 256>>>(xyz);
    vfeat_kernel<<<BN / 4, 256>>>(feature, xyz, Wv, bv);
    knn_thresh_kernel<<<BN / SBLK, SBLK>>>();
    dim3 kgrid(BN / SBLK, NSPLIT);
    knn_select_kernel<<<kgrid, SBLK>>>();
    knn_reduce_kernel<<<BN / RW, RW*32>>>();
    knn_fallback_kernel<<<BN / KBLK, KBLK>>>();
    attn_kernel<<<BN / 8, 256>>>(feature, Wsuf, bsuf, out);

    if (out_size > BN*OUTD) {
        int extra = out_size - BN*OUTD;
        tail_kernel<<<(extra + 255) / 256, 256>>>(out, out_size);
    }
}